// round 12
// baseline (speedup 1.0000x reference)
#include <cuda_runtime.h>
#include <cuda_bf16.h>
#include <math.h>
#include <stdint.h>

// ---------------- problem constants ----------------
#define HH 64
#define WW 64
#define PP 4096
#define CC 512
#define CGC 128
#define GG 4
#define KK 9
#define NH 8
#define DH 64
#define NPT 2048
#define NSLOT 36

// d_out layout: y | attn | xr_sel | sig
#define Y_OFF   0L
#define ATT_OFF 1048576L
#define XR_OFF  1196032L
#define SIG_OFF 38944768L

// ---------------- scratch ----------------
__device__ float    g_xT  [(long)PP * CC];
__device__ uint16_t g_xTh [(long)PP * CC];
__device__ uint16_t g_xTl [(long)PP * CC];
__device__ float    g_qT  [(long)PP * CC];
__device__ float    g_t1  [(long)GG * PP * CGC];
__device__ float    g_t2  [(long)GG * PP * CGC];
__device__ float2   g_meta[(long)NPT * NSLOT];
__device__ uint16_t g_qselh[(long)NPT * CC];
__device__ uint16_t g_qsell[(long)NPT * CC];
__device__ float    g_qbk [(long)NPT * NH];
__device__ float    g_qk  [(long)NPT * 4096];
__device__ uint16_t g_xsh [(long)NPT * 4096];
__device__ uint16_t g_xsl [(long)NPT * 4096];
__device__ uint16_t g_outTh[(long)NPT * CC];
__device__ uint16_t g_outTl[(long)NPT * CC];
__device__ uint16_t g_wh  [4L * 262144];   // wq | wv | wo | wkT
__device__ uint16_t g_wl  [4L * 262144];

// ---------------- helpers ----------------
__device__ __forceinline__ void split2(float v0, float v1, uint32_t& h, uint32_t& l) {
    uint32_t hw;
    asm("cvt.rn.bf16x2.f32 %0, %1, %2;" : "=r"(hw) : "f"(v1), "f"(v0));
    float f0 = __uint_as_float(hw << 16);
    float f1 = __uint_as_float(hw & 0xffff0000u);
    uint32_t lw;
    asm("cvt.rn.bf16x2.f32 %0, %1, %2;" : "=r"(lw) : "f"(v1 - f1), "f"(v0 - f0));
    h = hw; l = lw;
}
__device__ __forceinline__ void split1(float v, uint16_t& h, uint16_t& l) {
    __nv_bfloat16 hb = __float2bfloat16_rn(v);
    float hf = __bfloat162float(hb);
    __nv_bfloat16 lb = __float2bfloat16_rn(v - hf);
    h = __bfloat16_as_ushort(hb);
    l = __bfloat16_as_ushort(lb);
}
__device__ __forceinline__ void mma16(float* c, const uint32_t* a, const uint32_t* b) {
    asm volatile("mma.sync.aligned.m16n8k16.row.col.f32.bf16.bf16.f32 "
        "{%0,%1,%2,%3}, {%4,%5,%6,%7}, {%8,%9}, {%0,%1,%2,%3};"
        : "+f"(c[0]), "+f"(c[1]), "+f"(c[2]), "+f"(c[3])
        : "r"(a[0]), "r"(a[1]), "r"(a[2]), "r"(a[3]), "r"(b[0]), "r"(b[1]));
}
__device__ __forceinline__ void cpa16(uint32_t* smem, const void* gmem) {
    uint32_t s = (uint32_t)__cvta_generic_to_shared(smem);
    asm volatile("cp.async.ca.shared.global [%0], [%1], 16;" :: "r"(s), "l"(gmem));
}

// ---------------- weight pre-split (wq, wv, wo straight) ----------------
__global__ void split_w_kernel(const float* __restrict__ w0, const float* __restrict__ w1,
                               const float* __restrict__ w2)
{
    int t = blockIdx.x * blockDim.x + threadIdx.x;
    int m = t >> 17;
    int i = t & 131071;
    const float* src = (m == 0) ? w0 : (m == 1) ? w1 : w2;
    float2 v = ((const float2*)src)[i];
    uint32_t h, l;
    split2(v.x, v.y, h, l);
    ((uint32_t*)(g_wh + (long)m * 262144))[i] = h;
    ((uint32_t*)(g_wl + (long)m * 262144))[i] = l;
}

// ---------------- wk transpose + split ----------------
__global__ void wkT_kernel(const float* __restrict__ wk)
{
    __shared__ float tile[32][33];
    int o0 = blockIdx.x * 32, c0 = blockIdx.y * 32;
    int tx = threadIdx.x, ty = threadIdx.y;
    #pragma unroll
    for (int i = 0; i < 32; i += 8)
        tile[ty + i][tx] = wk[(o0 + ty + i) * 512 + c0 + tx];
    __syncthreads();
    #pragma unroll
    for (int i = 0; i < 32; i += 8) {
        int o = o0 + tx, c = c0 + ty + i;
        float v = tile[tx][ty + i];
        uint16_t h, l;
        split1(v, h, l);
        long dst = 786432L + (long)(o >> 6) * 32768 + (long)c * 64 + (o & 63);
        g_wh[dst] = h;
        g_wl[dst] = l;
    }
}

// ================= 4-stage cp.async split-bf16 GEMM =================
// C(M,N) = A(M,K) * B^T + bias. Pre-split bf16 hi/lo (3 cross terms).
// B[n][k] at Bg[n*ldb+k]. BN=64, BK=16, 256 threads = 8 warps (4m x 2n).
// BM in {64,128}. Dynamic smem: 4 stages x ((BM+64)*96 bytes).
template<int BM, int SPLITOUT>
__global__ __launch_bounds__(256) void gemm2_kernel(
    const uint16_t* __restrict__ Ah_g, const uint16_t* __restrict__ Al_g,
    const uint16_t* __restrict__ Bh_g, const uint16_t* __restrict__ Bl_g,
    float* __restrict__ C, uint16_t* __restrict__ Ch, uint16_t* __restrict__ Cl,
    const float* __restrict__ bias,
    int Kd, int lda, int ldb, int ldc,
    long aOff, long bOff, long cOff, long biasOff)
{
    const int S = 4, MI = BM / 64;
    const int AW = BM * 12, BW = 64 * 12;
    extern __shared__ __align__(16) uint32_t sm[];
    uint32_t* AhS = sm;                 // S*AW
    uint32_t* AlS = AhS + S * AW;
    uint32_t* BhS = AlS + S * AW;       // S*BW
    uint32_t* BlS = BhS + S * BW;

    int z = blockIdx.z;
    Ah_g += (long)z * aOff; Al_g += (long)z * aOff;
    Bh_g += (long)z * bOff; Bl_g += (long)z * bOff;
    if (SPLITOUT) { Ch += (long)z * cOff; Cl += (long)z * cOff; }
    else          { C  += (long)z * cOff; }
    if (bias) bias += (long)z * biasOff;

    int m0 = blockIdx.y * BM, n0 = blockIdx.x * 64;
    int tid = threadIdx.x, wid = tid >> 5, lane = tid & 31;
    int wm = (wid >> 1) * (MI * 16), wn = (wid & 1) * 32;
    int g = lane >> 2, tig = lane & 3;

    // ---- load mappings ----
    // BM=128: each thread does A-hi and A-lo for (row=tid>>1, half=tid&1)
    // BM=64:  each thread does ONE A cpa: row=tid&63, half=(tid>>6)&1, hi/lo=tid>>7
    int ar128 = tid >> 1, ah128 = tid & 1;
    int ar64 = tid & 63, ah64 = (tid >> 6) & 1;
    bool aHi64 = tid < 128;
    const uint16_t* apH = Ah_g + (long)(m0 + (BM == 128 ? ar128 : ar64)) * lda
                        + (BM == 128 ? ah128 : ah64) * 8;
    const uint16_t* apL = Al_g + (long)(m0 + (BM == 128 ? ar128 : ar64)) * lda
                        + (BM == 128 ? ah128 : ah64) * 8;
    int bt = tid & 127;
    int bn = bt >> 1, bh2 = bt & 1;
    bool bHi = tid < 128;
    const uint16_t* bp = (bHi ? Bh_g : Bl_g) + (long)(n0 + bn) * ldb + bh2 * 8;

    auto loadChunk = [&](int ch, int st) {
        if (BM == 128) {
            cpa16(AhS + st * AW + ar128 * 12 + ah128 * 4, apH + ch * 16);
            cpa16(AlS + st * AW + ar128 * 12 + ah128 * 4, apL + ch * 16);
        } else {
            uint32_t* dst = (aHi64 ? AhS : AlS) + st * AW + ar64 * 12 + ah64 * 4;
            cpa16(dst, (aHi64 ? apH : apL) + ch * 16);
        }
        uint32_t* bdst = (bHi ? BhS : BlS) + st * BW + bn * 12 + bh2 * 4;
        cpa16(bdst, bp + ch * 16);
    };

    float acc[MI][4][4];
    #pragma unroll
    for (int mi = 0; mi < MI; mi++)
        #pragma unroll
        for (int ni = 0; ni < 4; ni++)
            #pragma unroll
            for (int c = 0; c < 4; c++) acc[mi][ni][c] = 0.f;

    int nCh = Kd >> 4;
    // prologue: S-1 chunks in flight
    #pragma unroll
    for (int s = 0; s < S - 1; s++) {
        if (s < nCh) loadChunk(s, s);
        asm volatile("cp.async.commit_group;");
    }

    for (int ch = 0; ch < nCh; ch++) {
        int st = ch & (S - 1);
        asm volatile("cp.async.wait_group %0;" :: "n"(S - 2));
        __syncthreads();

        uint32_t ahf[MI][4], alf[MI][4], bhf[4][2], blf[4][2];
        #pragma unroll
        for (int mi = 0; mi < MI; mi++) {
            int mr = wm + mi * 16 + g;
            const uint32_t* ah = AhS + st * AW;
            const uint32_t* al = AlS + st * AW;
            ahf[mi][0] = ah[mr * 12 + tig];
            ahf[mi][1] = ah[(mr + 8) * 12 + tig];
            ahf[mi][2] = ah[mr * 12 + tig + 4];
            ahf[mi][3] = ah[(mr + 8) * 12 + tig + 4];
            alf[mi][0] = al[mr * 12 + tig];
            alf[mi][1] = al[(mr + 8) * 12 + tig];
            alf[mi][2] = al[mr * 12 + tig + 4];
            alf[mi][3] = al[(mr + 8) * 12 + tig + 4];
        }
        #pragma unroll
        for (int ni = 0; ni < 4; ni++) {
            int nr = wn + ni * 8 + g;
            bhf[ni][0] = BhS[st * BW + nr * 12 + tig];
            bhf[ni][1] = BhS[st * BW + nr * 12 + tig + 4];
            blf[ni][0] = BlS[st * BW + nr * 12 + tig];
            blf[ni][1] = BlS[st * BW + nr * 12 + tig + 4];
        }
        #pragma unroll
        for (int mi = 0; mi < MI; mi++)
            #pragma unroll
            for (int ni = 0; ni < 4; ni++) {
                mma16(acc[mi][ni], ahf[mi], bhf[ni]);
                mma16(acc[mi][ni], ahf[mi], blf[ni]);
                mma16(acc[mi][ni], alf[mi], bhf[ni]);
            }

        __syncthreads();
        int nx = ch + S - 1;
        if (nx < nCh) loadChunk(nx, nx & (S - 1));
        asm volatile("cp.async.commit_group;");
    }

    // ---- epilogue ----
    #pragma unroll
    for (int ni = 0; ni < 4; ni++) {
        int col = n0 + wn + ni * 8 + 2 * tig;
        float b0 = 0.f, b1 = 0.f;
        if (bias) { b0 = bias[col]; b1 = bias[col + 1]; }
        #pragma unroll
        for (int mi = 0; mi < MI; mi++) {
            int row = m0 + wm + mi * 16 + g;
            float v00 = acc[mi][ni][0] + b0, v01 = acc[mi][ni][1] + b1;
            float v10 = acc[mi][ni][2] + b0, v11 = acc[mi][ni][3] + b1;
            if (SPLITOUT) {
                uint16_t h, l;
                split1(v00, h, l); Ch[(long)row * ldc + col] = h;     Cl[(long)row * ldc + col] = l;
                split1(v01, h, l); Ch[(long)row * ldc + col + 1] = h; Cl[(long)row * ldc + col + 1] = l;
                split1(v10, h, l); Ch[(long)(row + 8) * ldc + col] = h;     Cl[(long)(row + 8) * ldc + col] = l;
                split1(v11, h, l); Ch[(long)(row + 8) * ldc + col + 1] = h; Cl[(long)(row + 8) * ldc + col + 1] = l;
            } else {
                *(float2*)(C + (long)row * ldc + col) = make_float2(v00, v01);
                *(float2*)(C + (long)(row + 8) * ldc + col) = make_float2(v10, v11);
            }
        }
    }
}

// ---------------- transpose x -> xT fp32 + split ----------------
__global__ void transpose_kernel(const float* __restrict__ x)
{
    __shared__ float tile[32][33];
    int pb = blockIdx.x * 32;
    int cb = blockIdx.y * 32;
    int tx = threadIdx.x, ty = threadIdx.y;
    #pragma unroll
    for (int i = 0; i < 32; i += 8)
        tile[ty + i][tx] = x[(long)(cb + ty + i) * PP + pb + tx];
    __syncthreads();
    #pragma unroll
    for (int i = 0; i < 32; i += 8) {
        float v = tile[tx][ty + i];
        long o = (long)(pb + ty + i) * CC + cb + tx;
        g_xT[o] = v;
        uint16_t h, l;
        split1(v, h, l);
        g_xTh[o] = h;
        g_xTl[o] = l;
    }
}

// ---------------- row-sliding depthwise3x3 + LN + GELU ----------------
__global__ __launch_bounds__(128) void dw_ln_gelu_kernel(
    const float* __restrict__ in, float* __restrict__ outp,
    const float* __restrict__ w, const float* __restrict__ cb,
    const float* __restrict__ gamma, const float* __restrict__ beta,
    long gStride, int pixStride)
{
    int half = blockIdx.x, y = blockIdx.y, g = blockIdx.z;
    int cc = threadIdx.x;
    int warp = cc >> 5, lane = cc & 31;
    const float* base = in + (long)g * gStride + cc;
    float w0 = w[cc * 9 + 0], w1 = w[cc * 9 + 1], w2 = w[cc * 9 + 2];
    float w3 = w[cc * 9 + 3], w4 = w[cc * 9 + 4], w5 = w[cc * 9 + 5];
    float w6 = w[cc * 9 + 6], w7 = w[cc * 9 + 7], w8 = w[cc * 9 + 8];
    float cbv = cb[cc], gv = gamma[cc], bev = beta[cc];
    __shared__ float r1[2][4], r2[2][4];

    int x0 = half * 32;
    float c0[3], c1[3], c2[3];
    auto ldcol = [&](int xx, float* col) {
        if ((unsigned)xx < 64u) {
            #pragma unroll
            for (int dy = 0; dy < 3; dy++) {
                int yy = y + dy - 1;
                col[dy] = ((unsigned)yy < 64u) ? base[(yy * 64 + xx) * pixStride] : 0.f;
            }
        } else { col[0] = col[1] = col[2] = 0.f; }
    };
    ldcol(x0 - 1, c0);
    ldcol(x0, c1);

    for (int i = 0; i < 32; i++) {
        int x = x0 + i;
        ldcol(x + 1, c2);
        float acc = cbv
            + w0 * c0[0] + w1 * c1[0] + w2 * c2[0]
            + w3 * c0[1] + w4 * c1[1] + w5 * c2[1]
            + w6 * c0[2] + w7 * c1[2] + w8 * c2[2];
        float s1 = acc, s2 = acc * acc;
        #pragma unroll
        for (int o = 16; o > 0; o >>= 1) {
            s1 += __shfl_xor_sync(0xffffffffu, s1, o);
            s2 += __shfl_xor_sync(0xffffffffu, s2, o);
        }
        int b = i & 1;
        if (lane == 0) { r1[b][warp] = s1; r2[b][warp] = s2; }
        __syncthreads();
        float t1s = r1[b][0] + r1[b][1] + r1[b][2] + r1[b][3];
        float t2s = r2[b][0] + r2[b][1] + r2[b][2] + r2[b][3];
        float mean = t1s * (1.f / 128.f);
        float var  = fmaxf(t2s * (1.f / 128.f) - mean * mean, 0.f);
        float nv = (acc - mean) * rsqrtf(var + 1e-5f) * gv + bev;
        float ge = 0.5f * nv * (1.f + erff(nv * 0.70710678118654752f));
        outp[((long)g * PP + y * 64 + x) * CGC + cc] = ge;
        c0[0] = c1[0]; c0[1] = c1[1]; c0[2] = c1[2];
        c1[0] = c2[0]; c1[1] = c2[1]; c1[2] = c2[2];
    }
}

// ---------------- offsets + coords; qsel split; qbk dot ----------------
__global__ void offset_kernel(const int* __restrict__ idx, const float* __restrict__ ow3,
                              const float* __restrict__ bk)
{
    int j = blockIdx.x;
    int tid = threadIdx.x;          // 128
    int warp = tid >> 5, lane = tid & 31;
    __shared__ float tv[128];
    __shared__ float offv[18];
    int iy = idx[2 * j], ix = idx[2 * j + 1];
    int p = iy * 64 + ix;

    {
        float4 v = ((const float4*)(g_qT + (long)p * CC))[tid];
        uint32_t h01, l01, h23, l23;
        split2(v.x, v.y, h01, l01);
        split2(v.z, v.w, h23, l23);
        ((uint2*)(g_qselh + (long)j * CC))[tid] = make_uint2(h01, h23);
        ((uint2*)(g_qsell + (long)j * CC))[tid] = make_uint2(l01, l23);
        float4 b = ((const float4*)bk)[tid];
        float s = v.x * b.x + v.y * b.y + v.z * b.z + v.w * b.w;
        #pragma unroll
        for (int o = 8; o > 0; o >>= 1)
            s += __shfl_xor_sync(0xffffffffu, s, o);
        if ((tid & 15) == 0) g_qbk[(long)j * NH + (tid >> 4)] = s;
    }

    for (int g = 0; g < GG; g++) {
        tv[tid] = g_t2[((long)g * PP + p) * CGC + tid];
        __syncthreads();
        for (int o = warp; o < 18; o += 4) {
            float s = 0.f;
            #pragma unroll
            for (int c = lane; c < 128; c += 32)
                s += tv[c] * ow3[o * 128 + c];
            #pragma unroll
            for (int off = 16; off > 0; off >>= 1)
                s += __shfl_xor_sync(0xffffffffu, s, off);
            if (lane == 0) offv[o] = s;
        }
        __syncthreads();
        if (tid < KK) {
            int k = tid, dy = k / 3, dx = k % 3;
            float oy = tanhf(offv[2 * k])     * (1.f / 32.f);
            float ox = tanhf(offv[2 * k + 1]) * (1.f / 32.f);
            int iyc = min(max(iy + dy - 1, 0), 63);
            int ixc = min(max(ix + dx - 1, 0), 63);
            float ry = (iyc + 0.5f) * (1.f / 32.f) - 1.f;
            float rx = (ixc + 0.5f) * (1.f / 32.f) - 1.f;
            float gy = (oy + ry + 1.f) * 31.5f;
            float gx = (ox + rx + 1.f) * 31.5f;
            g_meta[(long)j * NSLOT + g * KK + k] = make_float2(gy, gx);
        }
        __syncthreads();
    }
}

// ---------------- fused bilinear sampler + attention ----------------
__global__ __launch_bounds__(256) void sample_attn_kernel(float* __restrict__ out)
{
    __shared__ float xs_s[NSLOT * CGC];
    __shared__ float qk_s[4096];
    __shared__ float lg[72];
    __shared__ float at[72];
    int j = blockIdx.x, tid = threadIdx.x;  // 256
    int wid = tid >> 5, lane = tid & 31;
    int ct = tid & 127;
    int half = tid >> 7;
    float* xr = out + XR_OFF;
    int myg = ct >> 5;

    #pragma unroll
    for (int i = 0; i < 16; i++)
        qk_s[i * 256 + tid] = g_qk[(long)j * 4096 + i * 256 + tid];

    #pragma unroll 2
    for (int s2 = 0; s2 < 18; s2++) {
        int s = s2 * 2 + half;
        float2 m = g_meta[(long)j * NSLOT + s];
        float gy = m.x, gx = m.y;
        float y0 = floorf(gy), x0 = floorf(gx);
        float wy1 = gy - y0, wy0 = 1.f - wy1;
        float wx1 = gx - x0, wx0 = 1.f - wx1;
        float4 acc = make_float4(0.f, 0.f, 0.f, 0.f);
        #pragma unroll
        for (int t = 0; t < 4; t++) {
            float yy = y0 + (float)(t >> 1);
            float xx = x0 + (float)(t & 1);
            float w = ((t >> 1) ? wy1 : wy0) * ((t & 1) ? wx1 : wx0);
            bool ok = (yy >= 0.f) && (yy <= 63.f) && (xx >= 0.f) && (xx <= 63.f);
            if (ok && w != 0.f) {
                int yi = (int)yy, xi = (int)xx;
                const float4* row = (const float4*)(g_xT + (long)(yi * 64 + xi) * CC);
                float4 v = row[ct];
                acc.x += w * v.x; acc.y += w * v.y; acc.z += w * v.z; acc.w += w * v.w;
            }
        }
        ((float4*)(xr + ((long)j * NSLOT + s) * CC))[ct] = acc;
        if ((s / KK) == myg)
            *(float4*)&xs_s[s * CGC + 4 * ct - myg * CGC] = acc;
    }
    __syncthreads();

    {
        #pragma unroll
        for (int k = 0; k < KK; k++) {
            float s = 0.f;
            #pragma unroll
            for (int i = 0; i < 16; i++) {
                int cc = (i & 3) * 32 + lane;
                s += qk_s[wid * 512 + i * 32 + lane]
                   * xs_s[((i >> 2) * KK + k) * CGC + cc];
            }
            #pragma unroll
            for (int off = 16; off > 0; off >>= 1)
                s += __shfl_xor_sync(0xffffffffu, s, off);
            if (lane == 0)
                lg[wid * KK + k] = (s + g_qbk[(long)j * NH + wid]) * 0.125f;
        }
    }
    __syncthreads();

    if (tid < NH) {
        int h = tid;
        float mx = -1e30f;
        #pragma unroll
        for (int k = 0; k < KK; k++) mx = fmaxf(mx, lg[h * KK + k]);
        float e[KK], sm = 0.f;
        #pragma unroll
        for (int k = 0; k < KK; k++) { e[k] = expf(lg[h * KK + k] - mx); sm += e[k]; }
        float inv = 1.f / sm;
        #pragma unroll
        for (int k = 0; k < KK; k++) {
            float a = e[k] * inv;
            at[h * KK + k] = a;
            out[ATT_OFF + (long)h * NPT * KK + (long)j * KK + k] = a;
        }
    }
    __syncthreads();

    #pragma unroll
    for (int i = 0; i < 16; i++) {
        int o = i * 256 + tid;
        int h = o >> 9, c = o & 511, g = c >> 7, cc = c & 127;
        float s = 0.f;
        #pragma unroll
        for (int k = 0; k < KK; k++)
            s += at[h * KK + k] * xs_s[(g * KK + k) * CGC + cc];
        uint16_t hh, ll;
        split1(s, hh, ll);
        g_xsh[(long)j * 4096 + o] = hh;
        g_xsl[(long)j * 4096 + o] = ll;
    }
}

// ---------------- sigmoid of selected logit ----------------
__global__ void sig_kernel(const int* __restrict__ labels, float* __restrict__ out)
{
    int j = blockIdx.x * blockDim.x + threadIdx.x;
    if (j < NPT) {
        float v = out[(long)j * CC + labels[j]];
        out[SIG_OFF + j] = 1.f / (1.f + expf(-v));
    }
}

// ---------------- host ----------------
extern "C" void kernel_launch(void* const* d_in, const int* in_sizes, int n_in,
                              void* d_out, int out_size)
{
    const float* x   = (const float*)d_in[0];
    const int*   idx = (const int*)  d_in[1];
    const int*   lab = (const int*)  d_in[2];
    const float* wq  = (const float*)d_in[3];
    const float* bq  = (const float*)d_in[4];
    const float* wk  = (const float*)d_in[5];
    const float* bk  = (const float*)d_in[6];
    const float* wv  = (const float*)d_in[7];
    const float* bv  = (const float*)d_in[8];
    const float* wo  = (const float*)d_in[9];
    const float* bo  = (const float*)d_in[10];
    const float* ow1 = (const float*)d_in[11];
    const float* ob1 = (const float*)d_in[12];
    const float* g1  = (const float*)d_in[13];
    const float* b1  = (const float*)d_in[14];
    const float* ow2 = (const float*)d_in[15];
    const float* ob2 = (const float*)d_in[16];
    const float* g2  = (const float*)d_in[17];
    const float* b2  = (const float*)d_in[18];
    const float* ow3 = (const float*)d_in[19];
    float* out = (float*)d_out;

    float *qT, *t1, *t2, *qk;
    uint16_t *xTh, *xTl, *qsh, *qsl, *xsh, *xsl, *oth, *otl, *wh, *wl;
    cudaGetSymbolAddress((void**)&qT,  g_qT);
    cudaGetSymbolAddress((void**)&t1,  g_t1);
    cudaGetSymbolAddress((void**)&t2,  g_t2);
    cudaGetSymbolAddress((void**)&qk,  g_qk);
    cudaGetSymbolAddress((void**)&xTh, g_xTh);
    cudaGetSymbolAddress((void**)&xTl, g_xTl);
    cudaGetSymbolAddress((void**)&qsh, g_qselh);
    cudaGetSymbolAddress((void**)&qsl, g_qsell);
    cudaGetSymbolAddress((void**)&xsh, g_xsh);
    cudaGetSymbolAddress((void**)&xsl, g_xsl);
    cudaGetSymbolAddress((void**)&oth, g_outTh);
    cudaGetSymbolAddress((void**)&otl, g_outTl);
    cudaGetSymbolAddress((void**)&wh,  g_wh);
    cudaGetSymbolAddress((void**)&wl,  g_wl);
    uint16_t *wqh = wh,            *wql = wl;
    uint16_t *wvh = wh + 262144,   *wvl = wl + 262144;
    uint16_t *woh = wh + 524288,   *wol = wl + 524288;
    uint16_t *wkh = wh + 786432,   *wkl = wl + 786432;   // wkT layout

    const int SM128 = 4 * (128 + 64) * 96;   // 73728
    const int SM64  = 4 * (64 + 64) * 96;    // 49152
    cudaFuncSetAttribute(gemm2_kernel<128,0>,
                         cudaFuncAttributeMaxDynamicSharedMemorySize, SM128);
    cudaFuncSetAttribute(gemm2_kernel<64,0>,
                         cudaFuncAttributeMaxDynamicSharedMemorySize, SM64);
    cudaFuncSetAttribute(gemm2_kernel<64,1>,
                         cudaFuncAttributeMaxDynamicSharedMemorySize, SM64);

    // 0) weight split + wk transpose-split
    split_w_kernel<<<1536, 256>>>(wq, wv, wo);
    wkT_kernel<<<dim3(16, 16), dim3(32, 8)>>>(wk);

    // 1) x -> xT fp32 + split
    transpose_kernel<<<dim3(128, 16), dim3(32, 8)>>>(x);

    // 2) qT = xT @ wq^T + bq   (BM=64 -> 512 CTAs)
    gemm2_kernel<64, 0><<<dim3(8, 64, 1), 256, SM64>>>(xTh, xTl, wqh, wql,
        qT, nullptr, nullptr, bq, CC, CC, CC, CC, 0, 0, 0, 0);

    // 3) two depthwise+LN+GELU stages
    dw_ln_gelu_kernel<<<dim3(2, 64, 4), 128>>>(qT, t1, ow1, ob1, g1, b1,
        (long)CGC, CC);
    dw_ln_gelu_kernel<<<dim3(2, 64, 4), 128>>>(t1, t2, ow2, ob2, g2, b2,
        (long)PP * CGC, CGC);

    // 4) offsets -> coords; qsel split; qbk
    offset_kernel<<<NPT, 128>>>(idx, ow3, bk);

    // 5) qk = q_sel_h @ wkT_h (8 batched, Kd=64, BM=128 -> 1024 CTAs)
    gemm2_kernel<128, 0><<<dim3(8, 16, 8), 256, SM128>>>(qsh, qsl, wkh, wkl,
        qk, nullptr, nullptr, nullptr, DH, CC, DH, 4096, 64, 32768, 512, 0);

    // 6) fused sampling + attention
    sample_attn_kernel<<<NPT, 256>>>(out);

    // 7) outT = xsagg_h @ wv_h^T + bv (8 batched, BM=64 -> 256 CTAs, split out)
    gemm2_kernel<64, 1><<<dim3(1, 32, 8), 256, SM64>>>(xsh, xsl, wvh, wvl,
        nullptr, oth, otl, bv, CC, 4096, CC, CC, 512, 32768, 64, 64);

    // 8) y = outT @ wo^T + bo   (BM=64 -> 256 CTAs)
    gemm2_kernel<64, 0><<<dim3(8, 32, 1), 256, SM64>>>(oth, otl, woh, wol,
        out, nullptr, nullptr, bo, CC, CC, CC, CC, 0, 0, 0, 0);

    // 9) sig
    sig_kernel<<<8, 256>>>(lab, out);
}

// round 15
// speedup vs baseline: 1.1072x; 1.1072x over previous
#include <cuda_runtime.h>
#include <cuda_bf16.h>
#include <math.h>
#include <stdint.h>

// ---------------- problem constants ----------------
#define HH 64
#define WW 64
#define PP 4096
#define CC 512
#define CGC 128
#define GG 4
#define KK 9
#define NH 8
#define DH 64
#define NPT 2048
#define NSLOT 36

// d_out layout: y | attn | xr_sel | sig
#define Y_OFF   0L
#define ATT_OFF 1048576L
#define XR_OFF  1196032L
#define SIG_OFF 38944768L

// ---------------- scratch ----------------
__device__ float    g_xT  [(long)PP * CC];
__device__ uint16_t g_xTh [(long)PP * CC];
__device__ uint16_t g_xTl [(long)PP * CC];
__device__ float    g_qT  [(long)PP * CC];
__device__ float    g_t1  [(long)GG * PP * CGC];
__device__ float    g_t2  [(long)GG * PP * CGC];
__device__ float2   g_meta[(long)NPT * NSLOT];
__device__ uint16_t g_qselh[(long)NPT * CC];
__device__ uint16_t g_qsell[(long)NPT * CC];
__device__ float    g_qbk [(long)NPT * NH];
__device__ float    g_qk  [(long)NPT * 4096];
__device__ uint16_t g_xsh [(long)NPT * 4096];
__device__ uint16_t g_xsl [(long)NPT * 4096];
__device__ uint16_t g_outTh[(long)NPT * CC];
__device__ uint16_t g_outTl[(long)NPT * CC];
__device__ uint16_t g_wh  [4L * 262144];   // wq | wv | wo | wkT
__device__ uint16_t g_wl  [4L * 262144];

// ---------------- helpers ----------------
__device__ __forceinline__ void split2(float v0, float v1, uint32_t& h, uint32_t& l) {
    uint32_t hw;
    asm("cvt.rn.bf16x2.f32 %0, %1, %2;" : "=r"(hw) : "f"(v1), "f"(v0));
    float f0 = __uint_as_float(hw << 16);
    float f1 = __uint_as_float(hw & 0xffff0000u);
    uint32_t lw;
    asm("cvt.rn.bf16x2.f32 %0, %1, %2;" : "=r"(lw) : "f"(v1 - f1), "f"(v0 - f0));
    h = hw; l = lw;
}
__device__ __forceinline__ void split1(float v, uint16_t& h, uint16_t& l) {
    __nv_bfloat16 hb = __float2bfloat16_rn(v);
    float hf = __bfloat162float(hb);
    __nv_bfloat16 lb = __float2bfloat16_rn(v - hf);
    h = __bfloat16_as_ushort(hb);
    l = __bfloat16_as_ushort(lb);
}
__device__ __forceinline__ void mma16(float* c, const uint32_t* a, const uint32_t* b) {
    asm volatile("mma.sync.aligned.m16n8k16.row.col.f32.bf16.bf16.f32 "
        "{%0,%1,%2,%3}, {%4,%5,%6,%7}, {%8,%9}, {%0,%1,%2,%3};"
        : "+f"(c[0]), "+f"(c[1]), "+f"(c[2]), "+f"(c[3])
        : "r"(a[0]), "r"(a[1]), "r"(a[2]), "r"(a[3]), "r"(b[0]), "r"(b[1]));
}
__device__ __forceinline__ void cpa16(uint32_t* smem, const void* gmem) {
    uint32_t s = (uint32_t)__cvta_generic_to_shared(smem);
    asm volatile("cp.async.ca.shared.global [%0], [%1], 16;" :: "r"(s), "l"(gmem));
}

// ---------------- weight pre-split (wq, wv, wo straight) ----------------
__global__ void split_w_kernel(const float* __restrict__ w0, const float* __restrict__ w1,
                               const float* __restrict__ w2)
{
    int t = blockIdx.x * blockDim.x + threadIdx.x;
    int m = t >> 17;
    int i = t & 131071;
    const float* src = (m == 0) ? w0 : (m == 1) ? w1 : w2;
    float2 v = ((const float2*)src)[i];
    uint32_t h, l;
    split2(v.x, v.y, h, l);
    ((uint32_t*)(g_wh + (long)m * 262144))[i] = h;
    ((uint32_t*)(g_wl + (long)m * 262144))[i] = l;
}

// ---------------- wk transpose + split ----------------
__global__ void wkT_kernel(const float* __restrict__ wk)
{
    __shared__ float tile[32][33];
    int o0 = blockIdx.x * 32, c0 = blockIdx.y * 32;
    int tx = threadIdx.x, ty = threadIdx.y;
    #pragma unroll
    for (int i = 0; i < 32; i += 8)
        tile[ty + i][tx] = wk[(o0 + ty + i) * 512 + c0 + tx];
    __syncthreads();
    #pragma unroll
    for (int i = 0; i < 32; i += 8) {
        int o = o0 + tx, c = c0 + ty + i;
        float v = tile[tx][ty + i];
        uint16_t h, l;
        split1(v, h, l);
        long dst = 786432L + (long)(o >> 6) * 32768 + (long)c * 64 + (o & 63);
        g_wh[dst] = h;
        g_wl[dst] = l;
    }
}

// ================= 4-stage single-barrier cp.async split-bf16 GEMM =================
// C(M,N) = A(M,K) * B^T + bias. Pre-split bf16 hi/lo (3 cross terms).
// B[n][k] at Bg[n*ldb+k]. BM=128, BN=64, BK=16, 256 threads = 8 warps (4m x 2n).
// Pipeline: wait(S-2) -> barrier -> issue load(ch+S-1) -> compute(ch). ONE barrier/chunk.
template<int SPLITOUT>
__global__ __launch_bounds__(256) void gemm2_kernel(
    const uint16_t* __restrict__ Ah_g, const uint16_t* __restrict__ Al_g,
    const uint16_t* __restrict__ Bh_g, const uint16_t* __restrict__ Bl_g,
    float* __restrict__ C, uint16_t* __restrict__ Ch, uint16_t* __restrict__ Cl,
    const float* __restrict__ bias,
    int Kd, int lda, int ldb, int ldc,
    long aOff, long bOff, long cOff, long biasOff)
{
    const int S = 4, BM = 128;
    const int AW = BM * 12, BW = 64 * 12;
    extern __shared__ __align__(16) uint32_t sm[];
    uint32_t* AhS = sm;
    uint32_t* AlS = AhS + S * AW;
    uint32_t* BhS = AlS + S * AW;
    uint32_t* BlS = BhS + S * BW;

    int z = blockIdx.z;
    Ah_g += (long)z * aOff; Al_g += (long)z * aOff;
    Bh_g += (long)z * bOff; Bl_g += (long)z * bOff;
    if (SPLITOUT) { Ch += (long)z * cOff; Cl += (long)z * cOff; }
    else          { C  += (long)z * cOff; }
    if (bias) bias += (long)z * biasOff;

    int m0 = blockIdx.y * BM, n0 = blockIdx.x * 64;
    int tid = threadIdx.x, wid = tid >> 5, lane = tid & 31;
    int wm = (wid >> 1) * 32, wn = (wid & 1) * 32;
    int g = lane >> 2, tig = lane & 3;

    // load mapping: A hi+lo per thread (row=tid>>1, half=tid&1); B one cpa (hi tid<128, lo else)
    int ar = tid >> 1, ah2 = tid & 1;
    const uint16_t* apH = Ah_g + (long)(m0 + ar) * lda + ah2 * 8;
    const uint16_t* apL = Al_g + (long)(m0 + ar) * lda + ah2 * 8;
    int bt = tid & 127;
    int bn = bt >> 1, bh2 = bt & 1;
    bool bHi = tid < 128;
    const uint16_t* bp = (bHi ? Bh_g : Bl_g) + (long)(n0 + bn) * ldb + bh2 * 8;

    auto loadChunk = [&](int ch, int st) {
        cpa16(AhS + st * AW + ar * 12 + ah2 * 4, apH + ch * 16);
        cpa16(AlS + st * AW + ar * 12 + ah2 * 4, apL + ch * 16);
        uint32_t* bdst = (bHi ? BhS : BlS) + st * BW + bn * 12 + bh2 * 4;
        cpa16(bdst, bp + ch * 16);
    };

    float acc[2][4][4];
    #pragma unroll
    for (int mi = 0; mi < 2; mi++)
        #pragma unroll
        for (int ni = 0; ni < 4; ni++)
            #pragma unroll
            for (int c = 0; c < 4; c++) acc[mi][ni][c] = 0.f;

    int nCh = Kd >> 4;
    #pragma unroll
    for (int s = 0; s < S - 1; s++) {
        if (s < nCh) loadChunk(s, s);
        asm volatile("cp.async.commit_group;");
    }

    for (int ch = 0; ch < nCh; ch++) {
        int st = ch & (S - 1);
        asm volatile("cp.async.wait_group %0;" :: "n"(S - 2));
        __syncthreads();

        // front-issue next load into the stage consumed BEFORE this barrier
        int nx = ch + S - 1;
        if (nx < nCh) loadChunk(nx, nx & (S - 1));
        asm volatile("cp.async.commit_group;");

        uint32_t ahf[2][4], alf[2][4], bhf[4][2], blf[4][2];
        const uint32_t* ah = AhS + st * AW;
        const uint32_t* al = AlS + st * AW;
        #pragma unroll
        for (int mi = 0; mi < 2; mi++) {
            int mr = wm + mi * 16 + g;
            ahf[mi][0] = ah[mr * 12 + tig];
            ahf[mi][1] = ah[(mr + 8) * 12 + tig];
            ahf[mi][2] = ah[mr * 12 + tig + 4];
            ahf[mi][3] = ah[(mr + 8) * 12 + tig + 4];
            alf[mi][0] = al[mr * 12 + tig];
            alf[mi][1] = al[(mr + 8) * 12 + tig];
            alf[mi][2] = al[mr * 12 + tig + 4];
            alf[mi][3] = al[(mr + 8) * 12 + tig + 4];
        }
        #pragma unroll
        for (int ni = 0; ni < 4; ni++) {
            int nr = wn + ni * 8 + g;
            bhf[ni][0] = BhS[st * BW + nr * 12 + tig];
            bhf[ni][1] = BhS[st * BW + nr * 12 + tig + 4];
            blf[ni][0] = BlS[st * BW + nr * 12 + tig];
            blf[ni][1] = BlS[st * BW + nr * 12 + tig + 4];
        }
        #pragma unroll
        for (int mi = 0; mi < 2; mi++)
            #pragma unroll
            for (int ni = 0; ni < 4; ni++) {
                mma16(acc[mi][ni], ahf[mi], bhf[ni]);
                mma16(acc[mi][ni], ahf[mi], blf[ni]);
                mma16(acc[mi][ni], alf[mi], bhf[ni]);
            }
    }

    // ---- epilogue ----
    #pragma unroll
    for (int ni = 0; ni < 4; ni++) {
        int col = n0 + wn + ni * 8 + 2 * tig;
        float b0 = 0.f, b1 = 0.f;
        if (bias) { b0 = bias[col]; b1 = bias[col + 1]; }
        #pragma unroll
        for (int mi = 0; mi < 2; mi++) {
            int row = m0 + wm + mi * 16 + g;
            float v00 = acc[mi][ni][0] + b0, v01 = acc[mi][ni][1] + b1;
            float v10 = acc[mi][ni][2] + b0, v11 = acc[mi][ni][3] + b1;
            if (SPLITOUT) {
                uint16_t h, l;
                split1(v00, h, l); Ch[(long)row * ldc + col] = h;     Cl[(long)row * ldc + col] = l;
                split1(v01, h, l); Ch[(long)row * ldc + col + 1] = h; Cl[(long)row * ldc + col + 1] = l;
                split1(v10, h, l); Ch[(long)(row + 8) * ldc + col] = h;     Cl[(long)(row + 8) * ldc + col] = l;
                split1(v11, h, l); Ch[(long)(row + 8) * ldc + col + 1] = h; Cl[(long)(row + 8) * ldc + col + 1] = l;
            } else {
                *(float2*)(C + (long)row * ldc + col) = make_float2(v00, v01);
                *(float2*)(C + (long)(row + 8) * ldc + col) = make_float2(v10, v11);
            }
        }
    }
}

// ---------------- transpose x -> xT fp32 + split ----------------
__global__ void transpose_kernel(const float* __restrict__ x)
{
    __shared__ float tile[32][33];
    int pb = blockIdx.x * 32;
    int cb = blockIdx.y * 32;
    int tx = threadIdx.x, ty = threadIdx.y;
    #pragma unroll
    for (int i = 0; i < 32; i += 8)
        tile[ty + i][tx] = x[(long)(cb + ty + i) * PP + pb + tx];
    __syncthreads();
    #pragma unroll
    for (int i = 0; i < 32; i += 8) {
        float v = tile[tx][ty + i];
        long o = (long)(pb + ty + i) * CC + cb + tx;
        g_xT[o] = v;
        uint16_t h, l;
        split1(v, h, l);
        g_xTh[o] = h;
        g_xTl[o] = l;
    }
}

// ---------------- row-sliding depthwise3x3 + LN + GELU ----------------
__global__ __launch_bounds__(128) void dw_ln_gelu_kernel(
    const float* __restrict__ in, float* __restrict__ outp,
    const float* __restrict__ w, const float* __restrict__ cb,
    const float* __restrict__ gamma, const float* __restrict__ beta,
    long gStride, int pixStride)
{
    int half = blockIdx.x, y = blockIdx.y, g = blockIdx.z;
    int cc = threadIdx.x;
    int warp = cc >> 5, lane = cc & 31;
    const float* base = in + (long)g * gStride + cc;
    float w0 = w[cc * 9 + 0], w1 = w[cc * 9 + 1], w2 = w[cc * 9 + 2];
    float w3 = w[cc * 9 + 3], w4 = w[cc * 9 + 4], w5 = w[cc * 9 + 5];
    float w6 = w[cc * 9 + 6], w7 = w[cc * 9 + 7], w8 = w[cc * 9 + 8];
    float cbv = cb[cc], gv = gamma[cc], bev = beta[cc];
    __shared__ float r1[2][4], r2[2][4];

    int x0 = half * 32;
    float c0[3], c1[3], c2[3];
    auto ldcol = [&](int xx, float* col) {
        if ((unsigned)xx < 64u) {
            #pragma unroll
            for (int dy = 0; dy < 3; dy++) {
                int yy = y + dy - 1;
                col[dy] = ((unsigned)yy < 64u) ? base[(yy * 64 + xx) * pixStride] : 0.f;
            }
        } else { col[0] = col[1] = col[2] = 0.f; }
    };
    ldcol(x0 - 1, c0);
    ldcol(x0, c1);

    for (int i = 0; i < 32; i++) {
        int x = x0 + i;
        ldcol(x + 1, c2);
        float acc = cbv
            + w0 * c0[0] + w1 * c1[0] + w2 * c2[0]
            + w3 * c0[1] + w4 * c1[1] + w5 * c2[1]
            + w6 * c0[2] + w7 * c1[2] + w8 * c2[2];
        float s1 = acc, s2 = acc * acc;
        #pragma unroll
        for (int o = 16; o > 0; o >>= 1) {
            s1 += __shfl_xor_sync(0xffffffffu, s1, o);
            s2 += __shfl_xor_sync(0xffffffffu, s2, o);
        }
        int b = i & 1;
        if (lane == 0) { r1[b][warp] = s1; r2[b][warp] = s2; }
        __syncthreads();
        float t1s = r1[b][0] + r1[b][1] + r1[b][2] + r1[b][3];
        float t2s = r2[b][0] + r2[b][1] + r2[b][2] + r2[b][3];
        float mean = t1s * (1.f / 128.f);
        float var  = fmaxf(t2s * (1.f / 128.f) - mean * mean, 0.f);
        float nv = (acc - mean) * rsqrtf(var + 1e-5f) * gv + bev;
        float ge = 0.5f * nv * (1.f + erff(nv * 0.70710678118654752f));
        outp[((long)g * PP + y * 64 + x) * CGC + cc] = ge;
        c0[0] = c1[0]; c0[1] = c1[1]; c0[2] = c1[2];
        c1[0] = c2[0]; c1[1] = c2[1]; c1[2] = c2[2];
    }
}

// ---------------- offsets + coords; qsel split; qbk dot ----------------
__global__ void offset_kernel(const int* __restrict__ idx, const float* __restrict__ ow3,
                              const float* __restrict__ bk)
{
    int j = blockIdx.x;
    int tid = threadIdx.x;          // 128
    int warp = tid >> 5, lane = tid & 31;
    __shared__ float tv[128];
    __shared__ float offv[18];
    int iy = idx[2 * j], ix = idx[2 * j + 1];
    int p = iy * 64 + ix;

    {
        float4 v = ((const float4*)(g_qT + (long)p * CC))[tid];
        uint32_t h01, l01, h23, l23;
        split2(v.x, v.y, h01, l01);
        split2(v.z, v.w, h23, l23);
        ((uint2*)(g_qselh + (long)j * CC))[tid] = make_uint2(h01, h23);
        ((uint2*)(g_qsell + (long)j * CC))[tid] = make_uint2(l01, l23);
        float4 b = ((const float4*)bk)[tid];
        float s = v.x * b.x + v.y * b.y + v.z * b.z + v.w * b.w;
        #pragma unroll
        for (int o = 8; o > 0; o >>= 1)
            s += __shfl_xor_sync(0xffffffffu, s, o);
        if ((tid & 15) == 0) g_qbk[(long)j * NH + (tid >> 4)] = s;
    }

    for (int g = 0; g < GG; g++) {
        tv[tid] = g_t2[((long)g * PP + p) * CGC + tid];
        __syncthreads();
        for (int o = warp; o < 18; o += 4) {
            float s = 0.f;
            #pragma unroll
            for (int c = lane; c < 128; c += 32)
                s += tv[c] * ow3[o * 128 + c];
            #pragma unroll
            for (int off = 16; off > 0; off >>= 1)
                s += __shfl_xor_sync(0xffffffffu, s, off);
            if (lane == 0) offv[o] = s;
        }
        __syncthreads();
        if (tid < KK) {
            int k = tid, dy = k / 3, dx = k % 3;
            float oy = tanhf(offv[2 * k])     * (1.f / 32.f);
            float ox = tanhf(offv[2 * k + 1]) * (1.f / 32.f);
            int iyc = min(max(iy + dy - 1, 0), 63);
            int ixc = min(max(ix + dx - 1, 0), 63);
            float ry = (iyc + 0.5f) * (1.f / 32.f) - 1.f;
            float rx = (ixc + 0.5f) * (1.f / 32.f) - 1.f;
            float gy = (oy + ry + 1.f) * 31.5f;
            float gx = (ox + rx + 1.f) * 31.5f;
            g_meta[(long)j * NSLOT + g * KK + k] = make_float2(gy, gx);
        }
        __syncthreads();
    }
}

// ---------------- fused bilinear sampler + attention ----------------
__global__ __launch_bounds__(256) void sample_attn_kernel(float* __restrict__ out)
{
    __shared__ float xs_s[NSLOT * CGC];
    __shared__ float qk_s[4096];
    __shared__ float lg[72];
    __shared__ float at[72];
    int j = blockIdx.x, tid = threadIdx.x;  // 256
    int wid = tid >> 5, lane = tid & 31;
    int ct = tid & 127;
    int half = tid >> 7;
    float* xr = out + XR_OFF;
    int myg = ct >> 5;

    #pragma unroll
    for (int i = 0; i < 16; i++)
        qk_s[i * 256 + tid] = g_qk[(long)j * 4096 + i * 256 + tid];

    #pragma unroll 2
    for (int s2 = 0; s2 < 18; s2++) {
        int s = s2 * 2 + half;
        float2 m = g_meta[(long)j * NSLOT + s];
        float gy = m.x, gx = m.y;
        float y0 = floorf(gy), x0 = floorf(gx);
        float wy1 = gy - y0, wy0 = 1.f - wy1;
        float wx1 = gx - x0, wx0 = 1.f - wx1;
        float4 acc = make_float4(0.f, 0.f, 0.f, 0.f);
        #pragma unroll
        for (int t = 0; t < 4; t++) {
            float yy = y0 + (float)(t >> 1);
            float xx = x0 + (float)(t & 1);
            float w = ((t >> 1) ? wy1 : wy0) * ((t & 1) ? wx1 : wx0);
            bool ok = (yy >= 0.f) && (yy <= 63.f) && (xx >= 0.f) && (xx <= 63.f);
            if (ok && w != 0.f) {
                int yi = (int)yy, xi = (int)xx;
                const float4* row = (const float4*)(g_xT + (long)(yi * 64 + xi) * CC);
                float4 v = row[ct];
                acc.x += w * v.x; acc.y += w * v.y; acc.z += w * v.z; acc.w += w * v.w;
            }
        }
        ((float4*)(xr + ((long)j * NSLOT + s) * CC))[ct] = acc;
        if ((s / KK) == myg)
            *(float4*)&xs_s[s * CGC + 4 * ct - myg * CGC] = acc;
    }
    __syncthreads();

    {
        #pragma unroll
        for (int k = 0; k < KK; k++) {
            float s = 0.f;
            #pragma unroll
            for (int i = 0; i < 16; i++) {
                int cc = (i & 3) * 32 + lane;
                s += qk_s[wid * 512 + i * 32 + lane]
                   * xs_s[((i >> 2) * KK + k) * CGC + cc];
            }
            #pragma unroll
            for (int off = 16; off > 0; off >>= 1)
                s += __shfl_xor_sync(0xffffffffu, s, off);
            if (lane == 0)
                lg[wid * KK + k] = (s + g_qbk[(long)j * NH + wid]) * 0.125f;
        }
    }
    __syncthreads();

    if (tid < NH) {
        int h = tid;
        float mx = -1e30f;
        #pragma unroll
        for (int k = 0; k < KK; k++) mx = fmaxf(mx, lg[h * KK + k]);
        float e[KK], sm = 0.f;
        #pragma unroll
        for (int k = 0; k < KK; k++) { e[k] = expf(lg[h * KK + k] - mx); sm += e[k]; }
        float inv = 1.f / sm;
        #pragma unroll
        for (int k = 0; k < KK; k++) {
            float a = e[k] * inv;
            at[h * KK + k] = a;
            out[ATT_OFF + (long)h * NPT * KK + (long)j * KK + k] = a;
        }
    }
    __syncthreads();

    #pragma unroll
    for (int i = 0; i < 16; i++) {
        int o = i * 256 + tid;
        int h = o >> 9, c = o & 511, g = c >> 7, cc = c & 127;
        float s = 0.f;
        #pragma unroll
        for (int k = 0; k < KK; k++)
            s += at[h * KK + k] * xs_s[(g * KK + k) * CGC + cc];
        uint16_t hh, ll;
        split1(s, hh, ll);
        g_xsh[(long)j * 4096 + o] = hh;
        g_xsl[(long)j * 4096 + o] = ll;
    }
}

// ---------------- sigmoid of selected logit ----------------
__global__ void sig_kernel(const int* __restrict__ labels, float* __restrict__ out)
{
    int j = blockIdx.x * blockDim.x + threadIdx.x;
    if (j < NPT) {
        float v = out[(long)j * CC + labels[j]];
        out[SIG_OFF + j] = 1.f / (1.f + expf(-v));
    }
}

// ---------------- host ----------------
extern "C" void kernel_launch(void* const* d_in, const int* in_sizes, int n_in,
                              void* d_out, int out_size)
{
    const float* x   = (const float*)d_in[0];
    const int*   idx = (const int*)  d_in[1];
    const int*   lab = (const int*)  d_in[2];
    const float* wq  = (const float*)d_in[3];
    const float* bq  = (const float*)d_in[4];
    const float* wk  = (const float*)d_in[5];
    const float* bk  = (const float*)d_in[6];
    const float* wv  = (const float*)d_in[7];
    const float* bv  = (const float*)d_in[8];
    const float* wo  = (const float*)d_in[9];
    const float* bo  = (const float*)d_in[10];
    const float* ow1 = (const float*)d_in[11];
    const float* ob1 = (const float*)d_in[12];
    const float* g1  = (const float*)d_in[13];
    const float* b1  = (const float*)d_in[14];
    const float* ow2 = (const float*)d_in[15];
    const float* ob2 = (const float*)d_in[16];
    const float* g2  = (const float*)d_in[17];
    const float* b2  = (const float*)d_in[18];
    const float* ow3 = (const float*)d_in[19];
    float* out = (float*)d_out;

    float *qT, *t1, *t2, *qk;
    uint16_t *xTh, *xTl, *qsh, *qsl, *xsh, *xsl, *oth, *otl, *wh, *wl;
    cudaGetSymbolAddress((void**)&qT,  g_qT);
    cudaGetSymbolAddress((void**)&t1,  g_t1);
    cudaGetSymbolAddress((void**)&t2,  g_t2);
    cudaGetSymbolAddress((void**)&qk,  g_qk);
    cudaGetSymbolAddress((void**)&xTh, g_xTh);
    cudaGetSymbolAddress((void**)&xTl, g_xTl);
    cudaGetSymbolAddress((void**)&qsh, g_qselh);
    cudaGetSymbolAddress((void**)&qsl, g_qsell);
    cudaGetSymbolAddress((void**)&xsh, g_xsh);
    cudaGetSymbolAddress((void**)&xsl, g_xsl);
    cudaGetSymbolAddress((void**)&oth, g_outTh);
    cudaGetSymbolAddress((void**)&otl, g_outTl);
    cudaGetSymbolAddress((void**)&wh,  g_wh);
    cudaGetSymbolAddress((void**)&wl,  g_wl);
    uint16_t *wqh = wh,            *wql = wl;
    uint16_t *wvh = wh + 262144,   *wvl = wl + 262144;
    uint16_t *woh = wh + 524288,   *wol = wl + 524288;
    uint16_t *wkh = wh + 786432,   *wkl = wl + 786432;   // wkT layout

    const int SM128 = 4 * (128 + 64) * 96;   // 73728 bytes
    cudaFuncSetAttribute(gemm2_kernel<0>,
                         cudaFuncAttributeMaxDynamicSharedMemorySize, SM128);
    cudaFuncSetAttribute(gemm2_kernel<1>,
                         cudaFuncAttributeMaxDynamicSharedMemorySize, SM128);

    // 0) weight split + wk transpose-split
    split_w_kernel<<<1536, 256>>>(wq, wv, wo);
    wkT_kernel<<<dim3(16, 16), dim3(32, 8)>>>(wk);

    // 1) x -> xT fp32 + split
    transpose_kernel<<<dim3(128, 16), dim3(32, 8)>>>(x);

    // 2) qT = xT @ wq^T + bq   (BM=128 -> 256 CTAs)
    gemm2_kernel<0><<<dim3(8, 32, 1), 256, SM128>>>(xTh, xTl, wqh, wql,
        qT, nullptr, nullptr, bq, CC, CC, CC, CC, 0, 0, 0, 0);

    // 3) two depthwise+LN+GELU stages
    dw_ln_gelu_kernel<<<dim3(2, 64, 4), 128>>>(qT, t1, ow1, ob1, g1, b1,
        (long)CGC, CC);
    dw_ln_gelu_kernel<<<dim3(2, 64, 4), 128>>>(t1, t2, ow2, ob2, g2, b2,
        (long)PP * CGC, CGC);

    // 4) offsets -> coords; qsel split; qbk
    offset_kernel<<<NPT, 128>>>(idx, ow3, bk);

    // 5) qk = q_sel_h @ wkT_h (8 batched, Kd=64)
    gemm2_kernel<0><<<dim3(8, 16, 8), 256, SM128>>>(qsh, qsl, wkh, wkl,
        qk, nullptr, nullptr, nullptr, DH, CC, DH, 4096, 64, 32768, 512, 0);

    // 6) fused sampling + attention
    sample_attn_kernel<<<NPT, 256>>>(out);

    // 7) outT = xsagg_h @ wv_h^T + bv (8 batched, split output)
    gemm2_kernel<1><<<dim3(1, 16, 8), 256, SM128>>>(xsh, xsl, wvh, wvl,
        nullptr, oth, otl, bv, CC, 4096, CC, CC, 512, 32768, 64, 64);

    // 8) y = outT @ wo^T + bo
    gemm2_kernel<0><<<dim3(8, 16, 1), 256, SM128>>>(oth, otl, woh, wol,
        out, nullptr, nullptr, bo, CC, CC, CC, CC, 0, 0, 0, 0);

    // 9) sig
    sig_kernel<<<8, 256>>>(lab, out);
}

// round 17
// speedup vs baseline: 1.1740x; 1.0603x over previous
#include <cuda_runtime.h>
#include <cuda_bf16.h>
#include <math.h>
#include <stdint.h>

// ---------------- problem constants ----------------
#define HH 64
#define WW 64
#define PP 4096
#define CC 512
#define CGC 128
#define GG 4
#define KK 9
#define NH 8
#define DH 64
#define NPT 2048
#define NSLOT 36

// d_out layout: y | attn | xr_sel | sig
#define Y_OFF   0L
#define ATT_OFF 1048576L
#define XR_OFF  1196032L
#define SIG_OFF 38944768L

// ---------------- scratch ----------------
__device__ float    g_xT  [(long)PP * CC];
__device__ uint16_t g_xTh [(long)PP * CC];
__device__ uint16_t g_xTl [(long)PP * CC];
__device__ float    g_qT  [(long)PP * CC];
__device__ float    g_t1  [(long)GG * PP * CGC];
__device__ float    g_t2  [(long)GG * PP * CGC];
__device__ float2   g_meta[(long)NPT * NSLOT];
__device__ uint16_t g_qselh[(long)NPT * CC];
__device__ uint16_t g_qsell[(long)NPT * CC];
__device__ float    g_qbk [(long)NPT * NH];
__device__ float    g_qk  [(long)NPT * 4096];
__device__ uint16_t g_xsh [(long)NPT * 4096];
__device__ uint16_t g_xsl [(long)NPT * 4096];
__device__ uint16_t g_outTh[(long)NPT * CC];
__device__ uint16_t g_outTl[(long)NPT * CC];
__device__ uint16_t g_wh  [4L * 262144];   // wq | wv | wo | wkT
__device__ uint16_t g_wl  [4L * 262144];

// ---------------- helpers ----------------
__device__ __forceinline__ void split2(float v0, float v1, uint32_t& h, uint32_t& l) {
    uint32_t hw;
    asm("cvt.rn.bf16x2.f32 %0, %1, %2;" : "=r"(hw) : "f"(v1), "f"(v0));
    float f0 = __uint_as_float(hw << 16);
    float f1 = __uint_as_float(hw & 0xffff0000u);
    uint32_t lw;
    asm("cvt.rn.bf16x2.f32 %0, %1, %2;" : "=r"(lw) : "f"(v1 - f1), "f"(v0 - f0));
    h = hw; l = lw;
}
__device__ __forceinline__ void split1(float v, uint16_t& h, uint16_t& l) {
    __nv_bfloat16 hb = __float2bfloat16_rn(v);
    float hf = __bfloat162float(hb);
    __nv_bfloat16 lb = __float2bfloat16_rn(v - hf);
    h = __bfloat16_as_ushort(hb);
    l = __bfloat16_as_ushort(lb);
}
__device__ __forceinline__ void mma16(float* c, const uint32_t* a, const uint32_t* b) {
    asm volatile("mma.sync.aligned.m16n8k16.row.col.f32.bf16.bf16.f32 "
        "{%0,%1,%2,%3}, {%4,%5,%6,%7}, {%8,%9}, {%0,%1,%2,%3};"
        : "+f"(c[0]), "+f"(c[1]), "+f"(c[2]), "+f"(c[3])
        : "r"(a[0]), "r"(a[1]), "r"(a[2]), "r"(a[3]), "r"(b[0]), "r"(b[1]));
}
__device__ __forceinline__ void cpa16(uint32_t* smem, const void* gmem) {
    uint32_t s = (uint32_t)__cvta_generic_to_shared(smem);
    asm volatile("cp.async.ca.shared.global [%0], [%1], 16;" :: "r"(s), "l"(gmem));
}
__device__ __forceinline__ void ldsm4(uint32_t& r0, uint32_t& r1, uint32_t& r2, uint32_t& r3,
                                      uint32_t addr) {
    asm volatile("ldmatrix.sync.aligned.m8n8.x4.shared.b16 {%0,%1,%2,%3}, [%4];"
        : "=r"(r0), "=r"(r1), "=r"(r2), "=r"(r3) : "r"(addr));
}

// ---------------- weight pre-split (wq, wv, wo straight) ----------------
__global__ void split_w_kernel(const float* __restrict__ w0, const float* __restrict__ w1,
                               const float* __restrict__ w2)
{
    int t = blockIdx.x * blockDim.x + threadIdx.x;
    int m = t >> 17;
    int i = t & 131071;
    const float* src = (m == 0) ? w0 : (m == 1) ? w1 : w2;
    float2 v = ((const float2*)src)[i];
    uint32_t h, l;
    split2(v.x, v.y, h, l);
    ((uint32_t*)(g_wh + (long)m * 262144))[i] = h;
    ((uint32_t*)(g_wl + (long)m * 262144))[i] = l;
}

// ---------------- wk transpose + split ----------------
__global__ void wkT_kernel(const float* __restrict__ wk)
{
    __shared__ float tile[32][33];
    int o0 = blockIdx.x * 32, c0 = blockIdx.y * 32;
    int tx = threadIdx.x, ty = threadIdx.y;
    #pragma unroll
    for (int i = 0; i < 32; i += 8)
        tile[ty + i][tx] = wk[(o0 + ty + i) * 512 + c0 + tx];
    __syncthreads();
    #pragma unroll
    for (int i = 0; i < 32; i += 8) {
        int o = o0 + tx, c = c0 + ty + i;
        float v = tile[tx][ty + i];
        uint16_t h, l;
        split1(v, h, l);
        long dst = 786432L + (long)(o >> 6) * 32768 + (long)c * 64 + (o & 63);
        g_wh[dst] = h;
        g_wl[dst] = l;
    }
}

// ================= 4-stage cp.async + ldmatrix split-bf16 GEMM =================
// C(M,N) = A(M,K) * B^T + bias. Pre-split bf16 hi/lo (3 cross terms).
// B[n][k] at Bg[n*ldb+k]. BM=128, BN=64, BK=16, 256 threads = 8 warps (4m x 2n).
// Fragments via ldmatrix.x4 (row stride 48B -> conflict-free).
template<int SPLITOUT>
__global__ __launch_bounds__(256) void gemm2_kernel(
    const uint16_t* __restrict__ Ah_g, const uint16_t* __restrict__ Al_g,
    const uint16_t* __restrict__ Bh_g, const uint16_t* __restrict__ Bl_g,
    float* __restrict__ C, uint16_t* __restrict__ Ch, uint16_t* __restrict__ Cl,
    const float* __restrict__ bias,
    int Kd, int lda, int ldb, int ldc,
    long aOff, long bOff, long cOff, long biasOff)
{
    const int S = 4, BM = 128;
    const int AW = BM * 12, BW = 64 * 12;     // words per stage
    extern __shared__ __align__(16) uint32_t sm[];
    uint32_t* AhS = sm;
    uint32_t* AlS = AhS + S * AW;
    uint32_t* BhS = AlS + S * AW;
    uint32_t* BlS = BhS + S * BW;

    int z = blockIdx.z;
    Ah_g += (long)z * aOff; Al_g += (long)z * aOff;
    Bh_g += (long)z * bOff; Bl_g += (long)z * bOff;
    if (SPLITOUT) { Ch += (long)z * cOff; Cl += (long)z * cOff; }
    else          { C  += (long)z * cOff; }
    if (bias) bias += (long)z * biasOff;

    int m0 = blockIdx.y * BM, n0 = blockIdx.x * 64;
    int tid = threadIdx.x, wid = tid >> 5, lane = tid & 31;
    int wm = (wid >> 1) * 32, wn = (wid & 1) * 32;
    int g = lane >> 2, tig = lane & 3;

    // ---- cp.async load mapping ----
    int ar = tid >> 1, ah2 = tid & 1;
    const uint16_t* apH = Ah_g + (long)(m0 + ar) * lda + ah2 * 8;
    const uint16_t* apL = Al_g + (long)(m0 + ar) * lda + ah2 * 8;
    int bt = tid & 127;
    int bn = bt >> 1, bh2 = bt & 1;
    bool bHi = tid < 128;
    const uint16_t* bp = (bHi ? Bh_g : Bl_g) + (long)(n0 + bn) * ldb + bh2 * 8;

    auto loadChunk = [&](int ch, int st) {
        cpa16(AhS + st * AW + ar * 12 + ah2 * 4, apH + ch * 16);
        cpa16(AlS + st * AW + ar * 12 + ah2 * 4, apL + ch * 16);
        uint32_t* bdst = (bHi ? BhS : BlS) + st * BW + bn * 12 + bh2 * 4;
        cpa16(bdst, bp + ch * 16);
    };

    // ---- ldmatrix lane addresses (bytes, shared space) ----
    // A x4: matrices (m0-7,k0-7)(m8-15,k0-7)(m0-7,k8-15)(m8-15,k8-15)
    uint32_t aRowOff = (uint32_t)(wm + (lane & 7) + ((lane >> 3) & 1) * 8) * 48
                     + ((lane & 16) ? 16u : 0u);
    // B x4: matrices (n0-7,k0-7)(n0-7,k8-15)(n8-15,k0-7)(n8-15,k8-15)
    uint32_t bRowOff = (uint32_t)(wn + (lane & 7) + ((lane >> 4) & 1) * 8) * 48
                     + ((lane & 8) ? 16u : 0u);
    uint32_t shAh = (uint32_t)__cvta_generic_to_shared(AhS) + aRowOff;
    uint32_t shAl = (uint32_t)__cvta_generic_to_shared(AlS) + aRowOff;
    uint32_t shBh = (uint32_t)__cvta_generic_to_shared(BhS) + bRowOff;
    uint32_t shBl = (uint32_t)__cvta_generic_to_shared(BlS) + bRowOff;

    float acc[2][4][4];
    #pragma unroll
    for (int mi = 0; mi < 2; mi++)
        #pragma unroll
        for (int ni = 0; ni < 4; ni++)
            #pragma unroll
            for (int c = 0; c < 4; c++) acc[mi][ni][c] = 0.f;

    int nCh = Kd >> 4;
    #pragma unroll
    for (int s = 0; s < S - 1; s++) {
        if (s < nCh) loadChunk(s, s);
        asm volatile("cp.async.commit_group;");
    }

    for (int ch = 0; ch < nCh; ch++) {
        int st = ch & (S - 1);
        asm volatile("cp.async.wait_group %0;" :: "n"(S - 2));
        __syncthreads();

        // front-issue next load into the stage consumed BEFORE this barrier
        int nx = ch + S - 1;
        if (nx < nCh) loadChunk(nx, nx & (S - 1));
        asm volatile("cp.async.commit_group;");

        uint32_t aoff = (uint32_t)st * (AW * 4);
        uint32_t boff = (uint32_t)st * (BW * 4);

        uint32_t ahf[2][4], alf[2][4], bhf[4][2], blf[4][2];
        ldsm4(ahf[0][0], ahf[0][1], ahf[0][2], ahf[0][3], shAh + aoff);
        ldsm4(ahf[1][0], ahf[1][1], ahf[1][2], ahf[1][3], shAh + aoff + 768);
        ldsm4(alf[0][0], alf[0][1], alf[0][2], alf[0][3], shAl + aoff);
        ldsm4(alf[1][0], alf[1][1], alf[1][2], alf[1][3], shAl + aoff + 768);
        ldsm4(bhf[0][0], bhf[0][1], bhf[1][0], bhf[1][1], shBh + boff);
        ldsm4(bhf[2][0], bhf[2][1], bhf[3][0], bhf[3][1], shBh + boff + 768);
        ldsm4(blf[0][0], blf[0][1], blf[1][0], blf[1][1], shBl + boff);
        ldsm4(blf[2][0], blf[2][1], blf[3][0], blf[3][1], shBl + boff + 768);

        #pragma unroll
        for (int mi = 0; mi < 2; mi++)
            #pragma unroll
            for (int ni = 0; ni < 4; ni++) {
                mma16(acc[mi][ni], ahf[mi], bhf[ni]);
                mma16(acc[mi][ni], ahf[mi], blf[ni]);
                mma16(acc[mi][ni], alf[mi], bhf[ni]);
            }
    }

    // ---- epilogue ----
    #pragma unroll
    for (int ni = 0; ni < 4; ni++) {
        int col = n0 + wn + ni * 8 + 2 * tig;
        float b0 = 0.f, b1 = 0.f;
        if (bias) { b0 = bias[col]; b1 = bias[col + 1]; }
        #pragma unroll
        for (int mi = 0; mi < 2; mi++) {
            int row = m0 + wm + mi * 16 + g;
            float v00 = acc[mi][ni][0] + b0, v01 = acc[mi][ni][1] + b1;
            float v10 = acc[mi][ni][2] + b0, v11 = acc[mi][ni][3] + b1;
            if (SPLITOUT) {
                uint16_t h, l;
                split1(v00, h, l); Ch[(long)row * ldc + col] = h;     Cl[(long)row * ldc + col] = l;
                split1(v01, h, l); Ch[(long)row * ldc + col + 1] = h; Cl[(long)row * ldc + col + 1] = l;
                split1(v10, h, l); Ch[(long)(row + 8) * ldc + col] = h;     Cl[(long)(row + 8) * ldc + col] = l;
                split1(v11, h, l); Ch[(long)(row + 8) * ldc + col + 1] = h; Cl[(long)(row + 8) * ldc + col + 1] = l;
            } else {
                *(float2*)(C + (long)row * ldc + col) = make_float2(v00, v01);
                *(float2*)(C + (long)(row + 8) * ldc + col) = make_float2(v10, v11);
            }
        }
    }
}

// ---------------- transpose x -> xT fp32 + split ----------------
__global__ void transpose_kernel(const float* __restrict__ x)
{
    __shared__ float tile[32][33];
    int pb = blockIdx.x * 32;
    int cb = blockIdx.y * 32;
    int tx = threadIdx.x, ty = threadIdx.y;
    #pragma unroll
    for (int i = 0; i < 32; i += 8)
        tile[ty + i][tx] = x[(long)(cb + ty + i) * PP + pb + tx];
    __syncthreads();
    #pragma unroll
    for (int i = 0; i < 32; i += 8) {
        float v = tile[tx][ty + i];
        long o = (long)(pb + ty + i) * CC + cb + tx;
        g_xT[o] = v;
        uint16_t h, l;
        split1(v, h, l);
        g_xTh[o] = h;
        g_xTl[o] = l;
    }
}

// ---------------- row-sliding depthwise3x3 + LN + GELU ----------------
__global__ __launch_bounds__(128) void dw_ln_gelu_kernel(
    const float* __restrict__ in, float* __restrict__ outp,
    const float* __restrict__ w, const float* __restrict__ cb,
    const float* __restrict__ gamma, const float* __restrict__ beta,
    long gStride, int pixStride)
{
    int half = blockIdx.x, y = blockIdx.y, g = blockIdx.z;
    int cc = threadIdx.x;
    int warp = cc >> 5, lane = cc & 31;
    const float* base = in + (long)g * gStride + cc;
    float w0 = w[cc * 9 + 0], w1 = w[cc * 9 + 1], w2 = w[cc * 9 + 2];
    float w3 = w[cc * 9 + 3], w4 = w[cc * 9 + 4], w5 = w[cc * 9 + 5];
    float w6 = w[cc * 9 + 6], w7 = w[cc * 9 + 7], w8 = w[cc * 9 + 8];
    float cbv = cb[cc], gv = gamma[cc], bev = beta[cc];
    __shared__ float r1[2][4], r2[2][4];

    int x0 = half * 32;
    float c0[3], c1[3], c2[3];
    auto ldcol = [&](int xx, float* col) {
        if ((unsigned)xx < 64u) {
            #pragma unroll
            for (int dy = 0; dy < 3; dy++) {
                int yy = y + dy - 1;
                col[dy] = ((unsigned)yy < 64u) ? base[(yy * 64 + xx) * pixStride] : 0.f;
            }
        } else { col[0] = col[1] = col[2] = 0.f; }
    };
    ldcol(x0 - 1, c0);
    ldcol(x0, c1);

    for (int i = 0; i < 32; i++) {
        int x = x0 + i;
        ldcol(x + 1, c2);
        float acc = cbv
            + w0 * c0[0] + w1 * c1[0] + w2 * c2[0]
            + w3 * c0[1] + w4 * c1[1] + w5 * c2[1]
            + w6 * c0[2] + w7 * c1[2] + w8 * c2[2];
        float s1 = acc, s2 = acc * acc;
        #pragma unroll
        for (int o = 16; o > 0; o >>= 1) {
            s1 += __shfl_xor_sync(0xffffffffu, s1, o);
            s2 += __shfl_xor_sync(0xffffffffu, s2, o);
        }
        int b = i & 1;
        if (lane == 0) { r1[b][warp] = s1; r2[b][warp] = s2; }
        __syncthreads();
        float t1s = r1[b][0] + r1[b][1] + r1[b][2] + r1[b][3];
        float t2s = r2[b][0] + r2[b][1] + r2[b][2] + r2[b][3];
        float mean = t1s * (1.f / 128.f);
        float var  = fmaxf(t2s * (1.f / 128.f) - mean * mean, 0.f);
        float nv = (acc - mean) * rsqrtf(var + 1e-5f) * gv + bev;
        float ge = 0.5f * nv * (1.f + erff(nv * 0.70710678118654752f));
        outp[((long)g * PP + y * 64 + x) * CGC + cc] = ge;
        c0[0] = c1[0]; c0[1] = c1[1]; c0[2] = c1[2];
        c1[0] = c2[0]; c1[1] = c2[1]; c1[2] = c2[2];
    }
}

// ---------------- offsets + coords; qsel split; qbk dot ----------------
__global__ void offset_kernel(const int* __restrict__ idx, const float* __restrict__ ow3,
                              const float* __restrict__ bk)
{
    int j = blockIdx.x;
    int tid = threadIdx.x;          // 128
    int warp = tid >> 5, lane = tid & 31;
    __shared__ float tv[128];
    __shared__ float offv[18];
    int iy = idx[2 * j], ix = idx[2 * j + 1];
    int p = iy * 64 + ix;

    {
        float4 v = ((const float4*)(g_qT + (long)p * CC))[tid];
        uint32_t h01, l01, h23, l23;
        split2(v.x, v.y, h01, l01);
        split2(v.z, v.w, h23, l23);
        ((uint2*)(g_qselh + (long)j * CC))[tid] = make_uint2(h01, h23);
        ((uint2*)(g_qsell + (long)j * CC))[tid] = make_uint2(l01, l23);
        float4 b = ((const float4*)bk)[tid];
        float s = v.x * b.x + v.y * b.y + v.z * b.z + v.w * b.w;
        #pragma unroll
        for (int o = 8; o > 0; o >>= 1)
            s += __shfl_xor_sync(0xffffffffu, s, o);
        if ((tid & 15) == 0) g_qbk[(long)j * NH + (tid >> 4)] = s;
    }

    for (int g = 0; g < GG; g++) {
        tv[tid] = g_t2[((long)g * PP + p) * CGC + tid];
        __syncthreads();
        for (int o = warp; o < 18; o += 4) {
            float s = 0.f;
            #pragma unroll
            for (int c = lane; c < 128; c += 32)
                s += tv[c] * ow3[o * 128 + c];
            #pragma unroll
            for (int off = 16; off > 0; off >>= 1)
                s += __shfl_xor_sync(0xffffffffu, s, off);
            if (lane == 0) offv[o] = s;
        }
        __syncthreads();
        if (tid < KK) {
            int k = tid, dy = k / 3, dx = k % 3;
            float oy = tanhf(offv[2 * k])     * (1.f / 32.f);
            float ox = tanhf(offv[2 * k + 1]) * (1.f / 32.f);
            int iyc = min(max(iy + dy - 1, 0), 63);
            int ixc = min(max(ix + dx - 1, 0), 63);
            float ry = (iyc + 0.5f) * (1.f / 32.f) - 1.f;
            float rx = (ixc + 0.5f) * (1.f / 32.f) - 1.f;
            float gy = (oy + ry + 1.f) * 31.5f;
            float gx = (ox + rx + 1.f) * 31.5f;
            g_meta[(long)j * NSLOT + g * KK + k] = make_float2(gy, gx);
        }
        __syncthreads();
    }
}

// ---------------- fused bilinear sampler + attention ----------------
__global__ __launch_bounds__(256) void sample_attn_kernel(float* __restrict__ out)
{
    __shared__ float xs_s[NSLOT * CGC];
    __shared__ float qk_s[4096];
    __shared__ float lg[72];
    __shared__ float at[72];
    int j = blockIdx.x, tid = threadIdx.x;  // 256
    int wid = tid >> 5, lane = tid & 31;
    int ct = tid & 127;
    int half = tid >> 7;
    float* xr = out + XR_OFF;
    int myg = ct >> 5;

    #pragma unroll
    for (int i = 0; i < 16; i++)
        qk_s[i * 256 + tid] = g_qk[(long)j * 4096 + i * 256 + tid];

    #pragma unroll 2
    for (int s2 = 0; s2 < 18; s2++) {
        int s = s2 * 2 + half;
        float2 m = g_meta[(long)j * NSLOT + s];
        float gy = m.x, gx = m.y;
        float y0 = floorf(gy), x0 = floorf(gx);
        float wy1 = gy - y0, wy0 = 1.f - wy1;
        float wx1 = gx - x0, wx0 = 1.f - wx1;
        float4 acc = make_float4(0.f, 0.f, 0.f, 0.f);
        #pragma unroll
        for (int t = 0; t < 4; t++) {
            float yy = y0 + (float)(t >> 1);
            float xx = x0 + (float)(t & 1);
            float w = ((t >> 1) ? wy1 : wy0) * ((t & 1) ? wx1 : wx0);
            bool ok = (yy >= 0.f) && (yy <= 63.f) && (xx >= 0.f) && (xx <= 63.f);
            if (ok && w != 0.f) {
                int yi = (int)yy, xi = (int)xx;
                const float4* row = (const float4*)(g_xT + (long)(yi * 64 + xi) * CC);
                float4 v = row[ct];
                acc.x += w * v.x; acc.y += w * v.y; acc.z += w * v.z; acc.w += w * v.w;
            }
        }
        ((float4*)(xr + ((long)j * NSLOT + s) * CC))[ct] = acc;
        if ((s / KK) == myg)
            *(float4*)&xs_s[s * CGC + 4 * ct - myg * CGC] = acc;
    }
    __syncthreads();

    {
        #pragma unroll
        for (int k = 0; k < KK; k++) {
            float s = 0.f;
            #pragma unroll
            for (int i = 0; i < 16; i++) {
                int cc = (i & 3) * 32 + lane;
                s += qk_s[wid * 512 + i * 32 + lane]
                   * xs_s[((i >> 2) * KK + k) * CGC + cc];
            }
            #pragma unroll
            for (int off = 16; off > 0; off >>= 1)
                s += __shfl_xor_sync(0xffffffffu, s, off);
            if (lane == 0)
                lg[wid * KK + k] = (s + g_qbk[(long)j * NH + wid]) * 0.125f;
        }
    }
    __syncthreads();

    if (tid < NH) {
        int h = tid;
        float mx = -1e30f;
        #pragma unroll
        for (int k = 0; k < KK; k++) mx = fmaxf(mx, lg[h * KK + k]);
        float e[KK], sm = 0.f;
        #pragma unroll
        for (int k = 0; k < KK; k++) { e[k] = expf(lg[h * KK + k] - mx); sm += e[k]; }
        float inv = 1.f / sm;
        #pragma unroll
        for (int k = 0; k < KK; k++) {
            float a = e[k] * inv;
            at[h * KK + k] = a;
            out[ATT_OFF + (long)h * NPT * KK + (long)j * KK + k] = a;
        }
    }
    __syncthreads();

    #pragma unroll
    for (int i = 0; i < 16; i++) {
        int o = i * 256 + tid;
        int h = o >> 9, c = o & 511, g = c >> 7, cc = c & 127;
        float s = 0.f;
        #pragma unroll
        for (int k = 0; k < KK; k++)
            s += at[h * KK + k] * xs_s[(g * KK + k) * CGC + cc];
        uint16_t hh, ll;
        split1(s, hh, ll);
        g_xsh[(long)j * 4096 + o] = hh;
        g_xsl[(long)j * 4096 + o] = ll;
    }
}

// ---------------- sigmoid of selected logit ----------------
__global__ void sig_kernel(const int* __restrict__ labels, float* __restrict__ out)
{
    int j = blockIdx.x * blockDim.x + threadIdx.x;
    if (j < NPT) {
        float v = out[(long)j * CC + labels[j]];
        out[SIG_OFF + j] = 1.f / (1.f + expf(-v));
    }
}

// ---------------- host ----------------
extern "C" void kernel_launch(void* const* d_in, const int* in_sizes, int n_in,
                              void* d_out, int out_size)
{
    const float* x   = (const float*)d_in[0];
    const int*   idx = (const int*)  d_in[1];
    const int*   lab = (const int*)  d_in[2];
    const float* wq  = (const float*)d_in[3];
    const float* bq  = (const float*)d_in[4];
    const float* wk  = (const float*)d_in[5];
    const float* bk  = (const float*)d_in[6];
    const float* wv  = (const float*)d_in[7];
    const float* bv  = (const float*)d_in[8];
    const float* wo  = (const float*)d_in[9];
    const float* bo  = (const float*)d_in[10];
    const float* ow1 = (const float*)d_in[11];
    const float* ob1 = (const float*)d_in[12];
    const float* g1  = (const float*)d_in[13];
    const float* b1  = (const float*)d_in[14];
    const float* ow2 = (const float*)d_in[15];
    const float* ob2 = (const float*)d_in[16];
    const float* g2  = (const float*)d_in[17];
    const float* b2  = (const float*)d_in[18];
    const float* ow3 = (const float*)d_in[19];
    float* out = (float*)d_out;

    float *qT, *t1, *t2, *qk;
    uint16_t *xTh, *xTl, *qsh, *qsl, *xsh, *xsl, *oth, *otl, *wh, *wl;
    cudaGetSymbolAddress((void**)&qT,  g_qT);
    cudaGetSymbolAddress((void**)&t1,  g_t1);
    cudaGetSymbolAddress((void**)&t2,  g_t2);
    cudaGetSymbolAddress((void**)&qk,  g_qk);
    cudaGetSymbolAddress((void**)&xTh, g_xTh);
    cudaGetSymbolAddress((void**)&xTl, g_xTl);
    cudaGetSymbolAddress((void**)&qsh, g_qselh);
    cudaGetSymbolAddress((void**)&qsl, g_qsell);
    cudaGetSymbolAddress((void**)&xsh, g_xsh);
    cudaGetSymbolAddress((void**)&xsl, g_xsl);
    cudaGetSymbolAddress((void**)&oth, g_outTh);
    cudaGetSymbolAddress((void**)&otl, g_outTl);
    cudaGetSymbolAddress((void**)&wh,  g_wh);
    cudaGetSymbolAddress((void**)&wl,  g_wl);
    uint16_t *wqh = wh,            *wql = wl;
    uint16_t *wvh = wh + 262144,   *wvl = wl + 262144;
    uint16_t *woh = wh + 524288,   *wol = wl + 524288;
    uint16_t *wkh = wh + 786432,   *wkl = wl + 786432;   // wkT layout

    const int SM128 = 4 * (128 + 64) * 96;   // 73728 bytes
    cudaFuncSetAttribute(gemm2_kernel<0>,
                         cudaFuncAttributeMaxDynamicSharedMemorySize, SM128);
    cudaFuncSetAttribute(gemm2_kernel<1>,
                         cudaFuncAttributeMaxDynamicSharedMemorySize, SM128);

    // 0) weight split + wk transpose-split
    split_w_kernel<<<1536, 256>>>(wq, wv, wo);
    wkT_kernel<<<dim3(16, 16), dim3(32, 8)>>>(wk);

    // 1) x -> xT fp32 + split
    transpose_kernel<<<dim3(128, 16), dim3(32, 8)>>>(x);

    // 2) qT = xT @ wq^T + bq   (BM=128 -> 256 CTAs)
    gemm2_kernel<0><<<dim3(8, 32, 1), 256, SM128>>>(xTh, xTl, wqh, wql,
        qT, nullptr, nullptr, bq, CC, CC, CC, CC, 0, 0, 0, 0);

    // 3) two depthwise+LN+GELU stages
    dw_ln_gelu_kernel<<<dim3(2, 64, 4), 128>>>(qT, t1, ow1, ob1, g1, b1,
        (long)CGC, CC);
    dw_ln_gelu_kernel<<<dim3(2, 64, 4), 128>>>(t1, t2, ow2, ob2, g2, b2,
        (long)PP * CGC, CGC);

    // 4) offsets -> coords; qsel split; qbk
    offset_kernel<<<NPT, 128>>>(idx, ow3, bk);

    // 5) qk = q_sel_h @ wkT_h (8 batched, Kd=64)
    gemm2_kernel<0><<<dim3(8, 16, 8), 256, SM128>>>(qsh, qsl, wkh, wkl,
        qk, nullptr, nullptr, nullptr, DH, CC, DH, 4096, 64, 32768, 512, 0);

    // 6) fused sampling + attention
    sample_attn_kernel<<<NPT, 256>>>(out);

    // 7) outT = xsagg_h @ wv_h^T + bv (8 batched, split output)
    gemm2_kernel<1><<<dim3(1, 16, 8), 256, SM128>>>(xsh, xsl, wvh, wvl,
        nullptr, oth, otl, bv, CC, 4096, CC, CC, 512, 32768, 64, 64);

    // 8) y = outT @ wo^T + bo
    gemm2_kernel<0><<<dim3(8, 16, 1), 256, SM128>>>(oth, otl, woh, wol,
        out, nullptr, nullptr, bo, CC, CC, CC, CC, 0, 0, 0, 0);

    // 9) sig
    sig_kernel<<<8, 256>>>(lab, out);
}